// round 14
// baseline (speedup 1.0000x reference)
#include <cuda_runtime.h>
#include <cuda_bf16.h>
#include <cstdint>

#define B_    64
#define S_    512
#define H_    1024
#define HID_  512
#define K3_   3072   // 3*H
#define EPS_  1e-5f
#define KC_   48     // k per smem tile
#define NSLAB 64     // gemm k-slabs (one per kt)
#define GROWS 8      // rows per span work item
#define NSPAN 448    // persistent span CTAs

// Scratch (device globals: allocation-free, zero-initialized at load).
// INVARIANT: g_x and g_h are all-zero on entry to kernel_launch; the head
// kernel restores this invariant at the end of every call.
__device__ float g_x[B_ * K3_];                // concat embeddings      (768 KB)
__device__ float g_h[B_ * HID_];               // GEMM accumulator       (128 KB)

// ---------------------------------------------------------------------------
// Inline offset decode: detect int64 vs int32 source.
// ---------------------------------------------------------------------------
__device__ __forceinline__ int off_not64(const unsigned int* __restrict__ raw) {
    __shared__ int flag;
    if (threadIdx.x == 0) flag = 0;
    __syncthreads();
    for (int t = threadIdx.x; t < 160; t += blockDim.x)
        if (raw[2 * t + 1] != 0u) atomicExch(&flag, 1);
    __syncthreads();
    return flag;
}
__device__ __forceinline__ int off_get(const unsigned int* __restrict__ raw,
                                       int not64, int idx) {
    return not64 ? (int)raw[idx] : (int)raw[2 * idx];
}

// ---------------------------------------------------------------------------
// Range sum with 8 independent LDG.128 in flight per iteration.
// ---------------------------------------------------------------------------
__device__ __forceinline__ float4 range_sum(const float* __restrict__ base,
                                            int s0, int s1) {
    float4 a0 = make_float4(0.f, 0.f, 0.f, 0.f);
    float4 a1 = a0, a2 = a0, a3 = a0;
    int s = s0;
    for (; s + 7 <= s1; s += 8) {
        float4 v0 = *(const float4*)(base + (size_t)(s + 0) * H_);
        float4 v1 = *(const float4*)(base + (size_t)(s + 1) * H_);
        float4 v2 = *(const float4*)(base + (size_t)(s + 2) * H_);
        float4 v3 = *(const float4*)(base + (size_t)(s + 3) * H_);
        float4 v4 = *(const float4*)(base + (size_t)(s + 4) * H_);
        float4 v5 = *(const float4*)(base + (size_t)(s + 5) * H_);
        float4 v6 = *(const float4*)(base + (size_t)(s + 6) * H_);
        float4 v7 = *(const float4*)(base + (size_t)(s + 7) * H_);
        a0.x += v0.x + v4.x; a0.y += v0.y + v4.y;
        a0.z += v0.z + v4.z; a0.w += v0.w + v4.w;
        a1.x += v1.x + v5.x; a1.y += v1.y + v5.y;
        a1.z += v1.z + v5.z; a1.w += v1.w + v5.w;
        a2.x += v2.x + v6.x; a2.y += v2.y + v6.y;
        a2.z += v2.z + v6.z; a2.w += v2.w + v6.w;
        a3.x += v3.x + v7.x; a3.y += v3.y + v7.y;
        a3.z += v3.z + v7.z; a3.w += v3.w + v7.w;
    }
    for (; s + 3 <= s1; s += 4) {
        float4 v0 = *(const float4*)(base + (size_t)(s + 0) * H_);
        float4 v1 = *(const float4*)(base + (size_t)(s + 1) * H_);
        float4 v2 = *(const float4*)(base + (size_t)(s + 2) * H_);
        float4 v3 = *(const float4*)(base + (size_t)(s + 3) * H_);
        a0.x += v0.x; a0.y += v0.y; a0.z += v0.z; a0.w += v0.w;
        a1.x += v1.x; a1.y += v1.y; a1.z += v1.z; a1.w += v1.w;
        a2.x += v2.x; a2.y += v2.y; a2.z += v2.z; a2.w += v2.w;
        a3.x += v3.x; a3.y += v3.y; a3.z += v3.z; a3.w += v3.w;
    }
    for (; s <= s1; ++s) {
        float4 v = *(const float4*)(base + (size_t)s * H_);
        a0.x += v.x; a0.y += v.y; a0.z += v.z; a0.w += v.w;
    }
    a0.x += a1.x + a2.x + a3.x;
    a0.y += a1.y + a2.y + a3.y;
    a0.z += a1.z + a2.z + a3.z;
    a0.w += a1.w + a2.w + a3.w;
    return a0;
}

// ---------------------------------------------------------------------------
// Kernel 1: persistent balanced span means -> REDG into g_x.
// 448 CTAs self-schedule over ~2800 uniform 8-row work items built from the
// 128 (batch, span) segments. Register accumulation, flush on segment change.
// CTAs 0..63 also copy the pronoun row; all CTAs L2-prefetch a W1 slice.
// ---------------------------------------------------------------------------
__global__ void __launch_bounds__(256) span_partial(
        const float* __restrict__ bert,
        const unsigned int* __restrict__ raw,
        const float* __restrict__ W1) {
    int n64 = off_not64(raw);
    int t   = threadIdx.x;
    int cta = blockIdx.x;

    // W1 L2 prefetch: CTAs 0..383 each touch 16 KB (384 * 16 KB = 6 MB).
    if (cta < 384 && t < 128) {
        const char* ptr = (const char*)W1 + (size_t)cta * 16384 + t * 128;
        asm volatile("prefetch.global.L2 [%0];" :: "l"(ptr));
    }

    // Build per-segment item counts and exclusive prefix (smem).
    __shared__ int cnt[128];
    __shared__ int pre[129];
    if (t < 128) {
        int b = t >> 1, sp = t & 1;
        int s0 = off_get(raw, n64, b * 5 + sp * 2);
        int s1 = off_get(raw, n64, b * 5 + sp * 2 + 1);
        cnt[t] = (s1 - s0 + GROWS) / GROWS;     // ceil(len / GROWS), len >= 1
    }
    __syncthreads();
    if (t < 32) {
        int b0 = t * 4;
        int c0 = cnt[b0], c1 = cnt[b0 + 1], c2 = cnt[b0 + 2], c3 = cnt[b0 + 3];
        int s  = c0 + c1 + c2 + c3;
        int inc = s;
        #pragma unroll
        for (int d = 1; d < 32; d <<= 1) {
            int u = __shfl_up_sync(0xFFFFFFFFu, inc, d);
            if (t >= d) inc += u;
        }
        int excl = inc - s;
        pre[b0 + 0] = excl;
        pre[b0 + 1] = excl + c0;
        pre[b0 + 2] = excl + c0 + c1;
        pre[b0 + 3] = excl + c0 + c1 + c2;
        if (t == 31) pre[128] = inc;
    }
    __syncthreads();

    int total = pre[128];
    int i0 = (int)((long long)total * cta / NSPAN);
    int i1 = (int)((long long)total * (cta + 1) / NSPAN);

    float4 acc = make_float4(0.f, 0.f, 0.f, 0.f);
    int   curseg = -1, curs0 = 0, curs1 = 0;
    float curinv = 0.f;
    const float* base = nullptr;
    float* xflush = nullptr;

    for (int i = i0; i < i1; ++i) {
        // binary search: seg with pre[seg] <= i < pre[seg+1]
        int lo = 0, hi = 128;
        while (hi - lo > 1) {
            int mid = (lo + hi) >> 1;
            if (pre[mid] <= i) lo = mid; else hi = mid;
        }
        if (lo != curseg) {
            if (curseg >= 0) {               // flush previous segment
                atomicAdd(xflush + 0, acc.x * curinv);
                atomicAdd(xflush + 1, acc.y * curinv);
                atomicAdd(xflush + 2, acc.z * curinv);
                atomicAdd(xflush + 3, acc.w * curinv);
            }
            curseg = lo;
            int b = lo >> 1, sp = lo & 1;
            curs0 = off_get(raw, n64, b * 5 + sp * 2);
            curs1 = off_get(raw, n64, b * 5 + sp * 2 + 1);
            curinv = 1.0f / (float)(curs1 - curs0 + 1);
            base   = bert + (size_t)b * S_ * H_ + 4 * t;
            xflush = g_x + (size_t)b * K3_ + sp * H_ + 4 * t;
            acc = make_float4(0.f, 0.f, 0.f, 0.f);
        }
        int g  = i - pre[lo];
        int r0 = curs0 + g * GROWS;
        int r1 = min(curs1, r0 + GROWS - 1);
        float4 v = range_sum(base, r0, r1);
        acc.x += v.x; acc.y += v.y; acc.z += v.z; acc.w += v.w;
    }
    if (curseg >= 0) {
        atomicAdd(xflush + 0, acc.x * curinv);
        atomicAdd(xflush + 1, acc.y * curinv);
        atomicAdd(xflush + 2, acc.z * curinv);
        atomicAdd(xflush + 3, acc.w * curinv);
    }

    // Pronoun rows: CTA b copies row p_b (plain stores, no atomics).
    if (cta < B_) {
        int p = off_get(raw, n64, cta * 5 + 4);
        const float* src = bert + ((size_t)cta * S_ + p) * H_ + 4 * t;
        float4 v = *(const float4*)src;
        *(float4*)(g_x + (size_t)cta * K3_ + 2 * H_ + 4 * t) = v;
    }
}

// ---------------------------------------------------------------------------
// Kernel 2: GEMM x(64x3072) @ W1(3072x512), split-k over 64 kt chunks.
// grid(2 jt x 64 kt) = 128 CTAs, 256 threads. Block tile 64m x 256j x 48k.
// Thread tile 8m x 8j, FFMA2, x broadcast, conflict-free LDS.64 for W.
// Epilogue: RED.E.ADD.F32 into g_h.
// ---------------------------------------------------------------------------
#define FMA2(A, W, X) asm("fma.rn.f32x2 %0, %1, %2, %0;" \
                          : "+l"(A) : "l"(W), "l"(X))

__global__ void __launch_bounds__(256) gemm1(const float* __restrict__ W1) {
    extern __shared__ char smraw[];
    float2* xs2 = (float2*)smraw;                    // [KC_][64]  24 KB
    float*  ws  = (float*)(smraw + KC_ * 64 * 8);    // [KC_][256] 48 KB

    int jt  = blockIdx.x;           // 0..1
    int kt  = blockIdx.y;           // 0..63
    int tid = threadIdx.x;
    int jg  = tid & 31;             // lane: j-pair base
    int mg  = tid >> 5;             // warp: m-group of 8
    int jb  = jt * 256;
    int k0  = kt * KC_;
    int m0  = mg * 8;

    // W1 tile [KC_][256]: coalesced LDG.128 (L2-warm), conflict-free STS
    #pragma unroll
    for (int it = 0; it < 12; ++it) {
        int i = it * 256 + tid;
        int r = i >> 6, c = (i & 63) << 2;
        *(float4*)&ws[r * 256 + c] =
            *(const float4*)&W1[(size_t)(k0 + r) * HID_ + jb + c];
    }
    // x tile transposed + duplicated {v,v}: conflict-free STS
    #pragma unroll
    for (int it = 0; it < 3; ++it) {
        int i  = it * 256 + tid;
        int kq = i >> 6;                        // 0..11
        int m  = i & 63;
        float4 v = *(const float4*)&g_x[(size_t)m * K3_ + k0 + kq * 4];
        xs2[(kq * 4 + 0) * 64 + m] = make_float2(v.x, v.x);
        xs2[(kq * 4 + 1) * 64 + m] = make_float2(v.y, v.y);
        xs2[(kq * 4 + 2) * 64 + m] = make_float2(v.z, v.z);
        xs2[(kq * 4 + 3) * 64 + m] = make_float2(v.w, v.w);
    }
    __syncthreads();

    unsigned long long acc[8][4];   // [m][q]  j = jb + 2*jg + 64*q
    #pragma unroll
    for (int m = 0; m < 8; ++m)
        #pragma unroll
        for (int q = 0; q < 4; ++q) acc[m][q] = 0ull;

    const float*  wp = ws + 2 * jg;
    const float2* xp = xs2 + m0;

    // register double-buffer
    unsigned long long cw[4];
    ulonglong2 cx[4];
    #pragma unroll
    for (int q = 0; q < 4; ++q)
        cw[q] = *(const unsigned long long*)(wp + q * 64);
    #pragma unroll
    for (int i = 0; i < 4; ++i)
        cx[i] = *(const ulonglong2*)(xp + i * 2);

    #pragma unroll
    for (int k = 0; k < KC_; ++k) {
        unsigned long long nw[4];
        ulonglong2 nx[4];
        if (k < KC_ - 1) {
            const float*  wn = wp + (k + 1) * 256;
            const float2* xn = xp + (k + 1) * 64;
            #pragma unroll
            for (int q = 0; q < 4; ++q)
                nw[q] = *(const unsigned long long*)(wn + q * 64);
            #pragma unroll
            for (int i = 0; i < 4; ++i)
                nx[i] = *(const ulonglong2*)(xn + i * 2);
        }
        unsigned long long xm[8] = {cx[0].x, cx[0].y, cx[1].x, cx[1].y,
                                    cx[2].x, cx[2].y, cx[3].x, cx[3].y};
        #pragma unroll
        for (int m = 0; m < 8; ++m) {
            FMA2(acc[m][0], cw[0], xm[m]);
            FMA2(acc[m][1], cw[1], xm[m]);
            FMA2(acc[m][2], cw[2], xm[m]);
            FMA2(acc[m][3], cw[3], xm[m]);
        }
        #pragma unroll
        for (int q = 0; q < 4; ++q) cw[q] = nw[q];
        #pragma unroll
        for (int i = 0; i < 4; ++i) cx[i] = nx[i];
    }

    // Epilogue: no-return atomics into g_h (spread addresses)
    #pragma unroll
    for (int m = 0; m < 8; ++m) {
        float* row = &g_h[(m0 + m) * HID_ + jb + 2 * jg];
        #pragma unroll
        for (int q = 0; q < 4; ++q) {
            float2 v = *(float2*)&acc[m][q];
            atomicAdd(row + 64 * q,     v.x);
            atomicAdd(row + 64 * q + 1, v.y);
        }
    }
}

// ---------------------------------------------------------------------------
// Kernel 3: BN + leaky + @W2 + b2 -> out[64][3]; then restore the zero
// invariant on g_h (same thread that read it) and g_x (block-partitioned).
// grid(B), 512 thr.
// ---------------------------------------------------------------------------
__global__ void head(const float* __restrict__ b1,
                     const float* __restrict__ gamma,
                     const float* __restrict__ beta,
                     const float* __restrict__ rmean,
                     const float* __restrict__ rvar,
                     const float* __restrict__ W2,
                     const float* __restrict__ b2,
                     float* __restrict__ out) {
    int b = blockIdx.x;
    int j = threadIdx.x;               // 0..511

    float s  = g_h[b * HID_ + j];
    g_h[b * HID_ + j] = 0.f;           // re-zero own element (same thread)

    float sc = gamma[j] * rsqrtf(rvar[j] + EPS_);
    float h  = (s + b1[j] - rmean[j]) * sc + beta[j];
    h = (h >= 0.f) ? h : 0.01f * h;

    float o0 = h * W2[j * 3 + 0];
    float o1 = h * W2[j * 3 + 1];
    float o2 = h * W2[j * 3 + 2];

    #pragma unroll
    for (int d = 16; d > 0; d >>= 1) {
        o0 += __shfl_down_sync(0xFFFFFFFFu, o0, d);
        o1 += __shfl_down_sync(0xFFFFFFFFu, o1, d);
        o2 += __shfl_down_sync(0xFFFFFFFFu, o2, d);
    }

    __shared__ float red[16][3];
    if ((j & 31) == 0) {
        int w = j >> 5;
        red[w][0] = o0; red[w][1] = o1; red[w][2] = o2;
    }
    __syncthreads();
    if (j < 3) {
        float t = 0.f;
        #pragma unroll
        for (int w = 0; w < 16; ++w) t += red[w][j];
        out[b * 3 + j] = t + b2[j];
    }

    // Re-zero g_x: block b clears its own batch row (3072 floats, float4).
    float4 z4 = make_float4(0.f, 0.f, 0.f, 0.f);
    float* xr = g_x + (size_t)b * K3_;
    #pragma unroll
    for (int it = 0; it < 2; ++it) {
        int e = (it * 512 + j) * 4;
        if (e < K3_) *(float4*)(xr + e) = z4;
    }
}

// ---------------------------------------------------------------------------
extern "C" void kernel_launch(void* const* d_in, const int* in_sizes, int n_in,
                              void* d_out, int out_size) {
    const float*        bert  = (const float*)d_in[0];
    const unsigned int* offw  = (const unsigned int*)d_in[1];
    const float*        W1    = (const float*)d_in[2];
    const float*        b1    = (const float*)d_in[3];
    const float*        gamma = (const float*)d_in[4];
    const float*        beta  = (const float*)d_in[5];
    const float*        rmean = (const float*)d_in[6];
    const float*        rvar  = (const float*)d_in[7];
    const float*        W2    = (const float*)d_in[8];
    const float*        b2    = (const float*)d_in[9];
    float* out = (float*)d_out;

    const int gemm_smem = KC_ * 64 * 8 + KC_ * 256 * 4;  // 24 KB + 48 KB
    cudaFuncSetAttribute(gemm1, cudaFuncAttributeMaxDynamicSharedMemorySize,
                         gemm_smem);

    span_partial<<<NSPAN, 256>>>(bert, offw, W1);
    gemm1<<<dim3(2, NSLAB), 256, gemm_smem>>>(W1);
    head<<<B_, 512>>>(b1, gamma, beta, rmean, rvar, W2, b2, out);
}

// round 15
// speedup vs baseline: 1.1606x; 1.1606x over previous
#include <cuda_runtime.h>
#include <cuda_bf16.h>
#include <cstdint>

#define B_    64
#define S_    512
#define H_    1024
#define HID_  512
#define K3_   3072   // 3*H
#define EPS_  1e-5f
#define NCHUNK 16    // row chunks per span pass (512/32)
#define CHROWS 32    // rows per chunk
#define KC_   48     // k per smem tile
#define NSLAB 64     // gemm k-slabs (one per kt)

// Scratch (device globals: allocation-free, zero-initialized at load).
// INVARIANT: g_x and g_h are all-zero on entry to kernel_launch; the head
// kernel restores this invariant at the end of every call.
__device__ int   g_off[B_ * 5];                // normalized int32 offsets
__device__ float g_x[B_ * K3_];                // concat embeddings      (768 KB)
__device__ float g_h[B_ * HID_];               // GEMM accumulator       (128 KB)

// ---------------------------------------------------------------------------
// Kernel 0: normalize offsets once (auto-detect int64 vs int32 source).
// One block, 320 threads. Removes all per-block offset-decode preamble.
// ---------------------------------------------------------------------------
__global__ void decode_off(const unsigned int* __restrict__ raw) {
    __shared__ int not64;
    int t = threadIdx.x;                      // 0..319
    if (t == 0) not64 = 0;
    __syncthreads();
    if ((t & 1) && raw[t] != 0u) atomicExch(&not64, 1);
    __syncthreads();
    g_off[t] = not64 ? (int)raw[t] : (int)raw[2 * t];
}

// ---------------------------------------------------------------------------
// Range sum with 8 independent LDG.128 in flight per iteration.
// ---------------------------------------------------------------------------
__device__ __forceinline__ float4 range_sum(const float* __restrict__ base,
                                            int s0, int s1) {
    float4 a0 = make_float4(0.f, 0.f, 0.f, 0.f);
    float4 a1 = a0, a2 = a0, a3 = a0;
    int s = s0;
    for (; s + 7 <= s1; s += 8) {
        float4 v0 = *(const float4*)(base + (size_t)(s + 0) * H_);
        float4 v1 = *(const float4*)(base + (size_t)(s + 1) * H_);
        float4 v2 = *(const float4*)(base + (size_t)(s + 2) * H_);
        float4 v3 = *(const float4*)(base + (size_t)(s + 3) * H_);
        float4 v4 = *(const float4*)(base + (size_t)(s + 4) * H_);
        float4 v5 = *(const float4*)(base + (size_t)(s + 5) * H_);
        float4 v6 = *(const float4*)(base + (size_t)(s + 6) * H_);
        float4 v7 = *(const float4*)(base + (size_t)(s + 7) * H_);
        a0.x += v0.x + v4.x; a0.y += v0.y + v4.y;
        a0.z += v0.z + v4.z; a0.w += v0.w + v4.w;
        a1.x += v1.x + v5.x; a1.y += v1.y + v5.y;
        a1.z += v1.z + v5.z; a1.w += v1.w + v5.w;
        a2.x += v2.x + v6.x; a2.y += v2.y + v6.y;
        a2.z += v2.z + v6.z; a2.w += v2.w + v6.w;
        a3.x += v3.x + v7.x; a3.y += v3.y + v7.y;
        a3.z += v3.z + v7.z; a3.w += v3.w + v7.w;
    }
    for (; s + 3 <= s1; s += 4) {
        float4 v0 = *(const float4*)(base + (size_t)(s + 0) * H_);
        float4 v1 = *(const float4*)(base + (size_t)(s + 1) * H_);
        float4 v2 = *(const float4*)(base + (size_t)(s + 2) * H_);
        float4 v3 = *(const float4*)(base + (size_t)(s + 3) * H_);
        a0.x += v0.x; a0.y += v0.y; a0.z += v0.z; a0.w += v0.w;
        a1.x += v1.x; a1.y += v1.y; a1.z += v1.z; a1.w += v1.w;
        a2.x += v2.x; a2.y += v2.y; a2.z += v2.z; a2.w += v2.w;
        a3.x += v3.x; a3.y += v3.y; a3.z += v3.z; a3.w += v3.w;
    }
    for (; s <= s1; ++s) {
        float4 v = *(const float4*)(base + (size_t)s * H_);
        a0.x += v.x; a0.y += v.y; a0.z += v.z; a0.w += v.w;
    }
    a0.x += a1.x + a2.x + a3.x;
    a0.y += a1.y + a2.y + a3.y;
    a0.z += a1.z + a2.z + a3.z;
    a0.w += a1.w + a2.w + a3.w;
    return a0;
}

// ---------------------------------------------------------------------------
// Kernel 1: span partial means -> REDG into g_x; pronoun row copy.
// grid (B, NCHUNK=16), 256 thr, float4/thread, 32-row chunks.
// NO smem, NO syncthreads: offsets come pre-decoded from g_off (L2-hot).
// Each block also L2-prefetches its 6 KB W1 slice (free issue slots).
// ---------------------------------------------------------------------------
__global__ void span_partial(const float* __restrict__ bert,
                             const float* __restrict__ W1) {
    int b  = blockIdx.x;
    int z  = blockIdx.y;
    int t  = threadIdx.x;

    int a0 = g_off[b * 5 + 0], a1 = g_off[b * 5 + 1];
    int c0 = g_off[b * 5 + 2], c1 = g_off[b * 5 + 3];
    int p  = g_off[b * 5 + 4];
    int lo = z * CHROWS, hi = lo + CHROWS - 1;
    int sA0 = max(a0, lo), sA1 = min(a1, hi);
    int sB0 = max(c0, lo), sB1 = min(c1, hi);
    float inva = 1.0f / (float)(a1 - a0 + 1);
    float invb = 1.0f / (float)(c1 - c0 + 1);

    // L2 prefetch of this block's W1 slice: 6 KB x 1024 blocks = 6 MB.
    {
        int blk = b * NCHUNK + z;                   // 0..1023
        if (t < 48) {
            const char* ptr =
                (const char*)W1 + (size_t)blk * 6144 + (size_t)t * 128;
            asm volatile("prefetch.global.L2 [%0];" :: "l"(ptr));
        }
    }

    const float* base = bert + ((size_t)b * S_) * H_ + 4 * t;
    float* xr = g_x + (size_t)b * K3_ + 4 * t;

    if (sA1 >= sA0) {
        float4 acc = range_sum(base, sA0, sA1);
        atomicAdd(xr + 0, acc.x * inva);
        atomicAdd(xr + 1, acc.y * inva);
        atomicAdd(xr + 2, acc.z * inva);
        atomicAdd(xr + 3, acc.w * inva);
    }
    if (sB1 >= sB0) {
        float4 acc = range_sum(base, sB0, sB1);
        atomicAdd(xr + H_ + 0, acc.x * invb);
        atomicAdd(xr + H_ + 1, acc.y * invb);
        atomicAdd(xr + H_ + 2, acc.z * invb);
        atomicAdd(xr + H_ + 3, acc.w * invb);
    }
    // Pronoun row: the chunk that owns row p copies it (plain stores).
    if (p >= lo && p <= hi) {
        float4 v = *(const float4*)(base + (size_t)p * H_);
        *(float4*)(xr + 2 * H_) = v;
    }
}

// ---------------------------------------------------------------------------
// Kernel 2: GEMM x(64x3072) @ W1(3072x512), split-k over 64 kt chunks.
// grid(2 jt x 64 kt) = 128 CTAs, 256 threads. Block tile 64m x 256j x 48k.
// Thread tile 8m x 8j, FFMA2, x broadcast, conflict-free LDS.64 for W.
// Epilogue: RED.E.ADD.F32 into g_h.
// ---------------------------------------------------------------------------
#define FMA2(A, W, X) asm("fma.rn.f32x2 %0, %1, %2, %0;" \
                          : "+l"(A) : "l"(W), "l"(X))

__global__ void __launch_bounds__(256) gemm1(const float* __restrict__ W1) {
    extern __shared__ char smraw[];
    float2* xs2 = (float2*)smraw;                    // [KC_][64]  24 KB
    float*  ws  = (float*)(smraw + KC_ * 64 * 8);    // [KC_][256] 48 KB

    int jt  = blockIdx.x;           // 0..1
    int kt  = blockIdx.y;           // 0..63
    int tid = threadIdx.x;
    int jg  = tid & 31;             // lane: j-pair base
    int mg  = tid >> 5;             // warp: m-group of 8
    int jb  = jt * 256;
    int k0  = kt * KC_;
    int m0  = mg * 8;

    // W1 tile [KC_][256]: coalesced LDG.128 (L2-warm), conflict-free STS
    #pragma unroll
    for (int it = 0; it < 12; ++it) {
        int i = it * 256 + tid;
        int r = i >> 6, c = (i & 63) << 2;
        *(float4*)&ws[r * 256 + c] =
            *(const float4*)&W1[(size_t)(k0 + r) * HID_ + jb + c];
    }
    // x tile transposed + duplicated {v,v}: conflict-free STS
    #pragma unroll
    for (int it = 0; it < 3; ++it) {
        int i  = it * 256 + tid;
        int kq = i >> 6;                        // 0..11
        int m  = i & 63;
        float4 v = *(const float4*)&g_x[(size_t)m * K3_ + k0 + kq * 4];
        xs2[(kq * 4 + 0) * 64 + m] = make_float2(v.x, v.x);
        xs2[(kq * 4 + 1) * 64 + m] = make_float2(v.y, v.y);
        xs2[(kq * 4 + 2) * 64 + m] = make_float2(v.z, v.z);
        xs2[(kq * 4 + 3) * 64 + m] = make_float2(v.w, v.w);
    }
    __syncthreads();

    unsigned long long acc[8][4];   // [m][q]  j = jb + 2*jg + 64*q
    #pragma unroll
    for (int m = 0; m < 8; ++m)
        #pragma unroll
        for (int q = 0; q < 4; ++q) acc[m][q] = 0ull;

    const float*  wp = ws + 2 * jg;
    const float2* xp = xs2 + m0;

    // register double-buffer
    unsigned long long cw[4];
    ulonglong2 cx[4];
    #pragma unroll
    for (int q = 0; q < 4; ++q)
        cw[q] = *(const unsigned long long*)(wp + q * 64);
    #pragma unroll
    for (int i = 0; i < 4; ++i)
        cx[i] = *(const ulonglong2*)(xp + i * 2);

    #pragma unroll
    for (int k = 0; k < KC_; ++k) {
        unsigned long long nw[4];
        ulonglong2 nx[4];
        if (k < KC_ - 1) {
            const float*  wn = wp + (k + 1) * 256;
            const float2* xn = xp + (k + 1) * 64;
            #pragma unroll
            for (int q = 0; q < 4; ++q)
                nw[q] = *(const unsigned long long*)(wn + q * 64);
            #pragma unroll
            for (int i = 0; i < 4; ++i)
                nx[i] = *(const ulonglong2*)(xn + i * 2);
        }
        unsigned long long xm[8] = {cx[0].x, cx[0].y, cx[1].x, cx[1].y,
                                    cx[2].x, cx[2].y, cx[3].x, cx[3].y};
        #pragma unroll
        for (int m = 0; m < 8; ++m) {
            FMA2(acc[m][0], cw[0], xm[m]);
            FMA2(acc[m][1], cw[1], xm[m]);
            FMA2(acc[m][2], cw[2], xm[m]);
            FMA2(acc[m][3], cw[3], xm[m]);
        }
        #pragma unroll
        for (int q = 0; q < 4; ++q) cw[q] = nw[q];
        #pragma unroll
        for (int i = 0; i < 4; ++i) cx[i] = nx[i];
    }

    // Epilogue: no-return atomics into g_h (spread addresses)
    #pragma unroll
    for (int m = 0; m < 8; ++m) {
        float* row = &g_h[(m0 + m) * HID_ + jb + 2 * jg];
        #pragma unroll
        for (int q = 0; q < 4; ++q) {
            float2 v = *(float2*)&acc[m][q];
            atomicAdd(row + 64 * q,     v.x);
            atomicAdd(row + 64 * q + 1, v.y);
        }
    }
}

// ---------------------------------------------------------------------------
// Kernel 3: BN + leaky + @W2 + b2 -> out[64][3]; then restore the zero
// invariant on g_h (same thread that read it) and g_x (block-partitioned).
// grid(B), 512 thr.
// ---------------------------------------------------------------------------
__global__ void head(const float* __restrict__ b1,
                     const float* __restrict__ gamma,
                     const float* __restrict__ beta,
                     const float* __restrict__ rmean,
                     const float* __restrict__ rvar,
                     const float* __restrict__ W2,
                     const float* __restrict__ b2,
                     float* __restrict__ out) {
    int b = blockIdx.x;
    int j = threadIdx.x;               // 0..511

    float s  = g_h[b * HID_ + j];
    g_h[b * HID_ + j] = 0.f;           // re-zero own element (same thread)

    float sc = gamma[j] * rsqrtf(rvar[j] + EPS_);
    float h  = (s + b1[j] - rmean[j]) * sc + beta[j];
    h = (h >= 0.f) ? h : 0.01f * h;

    float o0 = h * W2[j * 3 + 0];
    float o1 = h * W2[j * 3 + 1];
    float o2 = h * W2[j * 3 + 2];

    #pragma unroll
    for (int d = 16; d > 0; d >>= 1) {
        o0 += __shfl_down_sync(0xFFFFFFFFu, o0, d);
        o1 += __shfl_down_sync(0xFFFFFFFFu, o1, d);
        o2 += __shfl_down_sync(0xFFFFFFFFu, o2, d);
    }

    __shared__ float red[16][3];
    if ((j & 31) == 0) {
        int w = j >> 5;
        red[w][0] = o0; red[w][1] = o1; red[w][2] = o2;
    }
    __syncthreads();
    if (j < 3) {
        float t = 0.f;
        #pragma unroll
        for (int w = 0; w < 16; ++w) t += red[w][j];
        out[b * 3 + j] = t + b2[j];
    }

    // Re-zero g_x: block b clears its own batch row (3072 floats, float4).
    float4 z4 = make_float4(0.f, 0.f, 0.f, 0.f);
    float* xr = g_x + (size_t)b * K3_;
    #pragma unroll
    for (int it = 0; it < 2; ++it) {
        int e = (it * 512 + j) * 4;
        if (e < K3_) *(float4*)(xr + e) = z4;
    }
}

// ---------------------------------------------------------------------------
extern "C" void kernel_launch(void* const* d_in, const int* in_sizes, int n_in,
                              void* d_out, int out_size) {
    const float*        bert  = (const float*)d_in[0];
    const unsigned int* offw  = (const unsigned int*)d_in[1];
    const float*        W1    = (const float*)d_in[2];
    const float*        b1    = (const float*)d_in[3];
    const float*        gamma = (const float*)d_in[4];
    const float*        beta  = (const float*)d_in[5];
    const float*        rmean = (const float*)d_in[6];
    const float*        rvar  = (const float*)d_in[7];
    const float*        W2    = (const float*)d_in[8];
    const float*        b2    = (const float*)d_in[9];
    float* out = (float*)d_out;

    const int gemm_smem = KC_ * 64 * 8 + KC_ * 256 * 4;  // 24 KB + 48 KB
    cudaFuncSetAttribute(gemm1, cudaFuncAttributeMaxDynamicSharedMemorySize,
                         gemm_smem);

    decode_off<<<1, B_ * 5>>>(offw);
    span_partial<<<dim3(B_, NCHUNK), 256>>>(bert, W1);
    gemm1<<<dim3(2, NSLAB), 256, gemm_smem>>>(W1);
    head<<<B_, 512>>>(b1, gamma, beta, rmean, rvar, W2, b2, out);
}